// round 13
// baseline (speedup 1.0000x reference)
#include <cuda_runtime.h>
#include <cuda_fp16.h>
#include <math.h>
#include <stdint.h>

// ---------------- problem constants ----------------
#define SEQ   256
#define BATCH 32
#define HID   1024
#define G4    4096
#define KDIM  1024
#define MROWS (SEQ*BATCH)

#define NCTA  128           // persistent grid (2 dirs x 64 j-tiles of 64 gate cols)
#define DCTA  64            // CTAs per direction

// output layout inside d_out (floats)
#define OUT_HALL   (SEQ*BATCH*2*HID)
#define OUT_CALL   (OUT_HALL + 2*BATCH*2*HID)

// ---------------- device scratch ----------------
__device__ float  g_xg  [2][SEQ*BATCH*G4];       // per-direction xg
__device__ __half g_Wih16[2][2][G4*KDIM];        // gate-permuted W_ih fp16 (input GEMM)
__device__ __half g_Whh16[2][2][G4*KDIM];        // gate-permuted W_hh fp16 (recurrence)
__device__ __half g_Axh[2][MROWS*KDIM];          // GEMM A hi ([0]=x layer0, [dir] layer1)
__device__ __half g_Axl[2][MROWS*KDIM];          // GEMM A lo
__device__ __half g_h16[2*2*BATCH*HID];          // [dir][pp][b][k] recurrent h fp16
// barrier slots, each padded to its own 128B line: slot i lives at g_sync[i*32]
//   slots 0..15 : group counters (d*8+grp) ; 16+d : root counters ; 18+d : gen flags
__device__ unsigned g_sync[1024];

// ---------------- sync / async-copy helpers ----------------
__device__ __forceinline__ unsigned ld_acq(const unsigned* p) {
    unsigned v; asm volatile("ld.acquire.gpu.u32 %0, [%1];" : "=r"(v) : "l"(p) : "memory"); return v;
}
__device__ __forceinline__ void st_rel(unsigned* p, unsigned v) {
    asm volatile("st.release.gpu.u32 [%0], %1;" :: "l"(p), "r"(v) : "memory");
}
__device__ __forceinline__ unsigned atom_add_acqrel(unsigned* p, unsigned v) {
    unsigned o; asm volatile("atom.acq_rel.gpu.add.u32 %0, [%1], %2;"
                             : "=r"(o) : "l"(p), "r"(v) : "memory"); return o;
}
__device__ __forceinline__ void cp16(uint32_t s, const void* g) {
    asm volatile("cp.async.cg.shared.global [%0], [%1], 16;" :: "r"(s), "l"(g));
}
__device__ __forceinline__ void cp_commit() { asm volatile("cp.async.commit_group;"); }
__device__ __forceinline__ void cp_wait1()  { asm volatile("cp.async.wait_group 1;" ::: "memory"); }
__device__ __forceinline__ void cp_wait0()  { asm volatile("cp.async.wait_group 0;" ::: "memory"); }
#define BAR_SYNC(id, n) asm volatile("bar.sync %0, %1;" :: "r"(id), "r"(n) : "memory")

__device__ __forceinline__ uint32_t smem_u32(const void* p) {
    return (uint32_t)__cvta_generic_to_shared(p);
}

// ---------------- mma.sync / ldmatrix helpers (base PTX, sm_80+) ----------------
__device__ __forceinline__ void ldsm_x4(uint32_t& r0, uint32_t& r1, uint32_t& r2, uint32_t& r3,
                                        uint32_t addr) {
    asm volatile("ldmatrix.sync.aligned.m8n8.x4.shared.b16 {%0,%1,%2,%3}, [%4];"
                 : "=r"(r0), "=r"(r1), "=r"(r2), "=r"(r3) : "r"(addr));
}
__device__ __forceinline__ void ldsm_x2(uint32_t& r0, uint32_t& r1, uint32_t addr) {
    asm volatile("ldmatrix.sync.aligned.m8n8.x2.shared.b16 {%0,%1}, [%2];"
                 : "=r"(r0), "=r"(r1) : "r"(addr));
}
__device__ __forceinline__ void mma_f16(float& c0, float& c1, float& c2, float& c3,
                                        uint32_t a0, uint32_t a1, uint32_t a2, uint32_t a3,
                                        uint32_t b0, uint32_t b1) {
    asm volatile("mma.sync.aligned.m16n8k16.row.col.f32.f16.f16.f32 "
                 "{%0,%1,%2,%3}, {%4,%5,%6,%7}, {%8,%9}, {%0,%1,%2,%3};"
                 : "+f"(c0), "+f"(c1), "+f"(c2), "+f"(c3)
                 : "r"(a0), "r"(a1), "r"(a2), "r"(a3), "r"(b0), "r"(b1));
}

// ---------------- split helper ----------------
__device__ __forceinline__ void split_f16(float x, __half& h, __half& l) {
    h = __float2half_rn(x);
    l = __float2half_rn(x - __half2float(h));
}

// ---------------- 1a) weight gate-permute to fp16: row g*H+h -> 4h+g ----------------
__global__ __launch_bounds__(256) void repack_w(
    const float* __restrict__ wihf, const float* __restrict__ whhf,
    const float* __restrict__ wihb, const float* __restrict__ whhb)
{
    int p = blockIdx.x;
    int m = blockIdx.y;
    int dir   = m >> 2;
    int typ   = (m >> 1) & 1;          // 0 = ih, 1 = hh
    int layer = m & 1;
    int srow  = (p & 3) * HID + (p >> 2);

    const float* base = dir ? (typ ? whhb : wihb) : (typ ? whhf : wihf);
    const float* src  = base + (size_t)layer * G4 * KDIM;
    __half* dst = (typ ? g_Whh16[layer][dir] : g_Wih16[layer][dir]) + (size_t)p * KDIM;

    int c = threadIdx.x * 4;
    float4 v = *(const float4*)&src[(size_t)srow * KDIM + c];
    __half2 a = {__float2half_rn(v.x), __float2half_rn(v.y)};
    __half2 b = {__float2half_rn(v.z), __float2half_rn(v.w)};
    *(__half2*)&dst[c]     = a;
    *(__half2*)&dst[c + 2] = b;
}

// ---------------- 1b) fp32 x -> fp16 hi/lo for layer-0 GEMM A ----------------
__global__ __launch_bounds__(256) void conv_x_f16(const float* __restrict__ x)
{
    size_t i = ((size_t)blockIdx.x * 256 + threadIdx.x) * 4;
    float4 v = *(const float4*)&x[i];
    __half h0, l0, h1, l1, h2, l2, h3, l3;
    split_f16(v.x, h0, l0); split_f16(v.y, h1, l1);
    split_f16(v.z, h2, l2); split_f16(v.w, h3, l3);
    __half2 hh0 = {h0, h1}, hh1 = {h2, h3};
    __half2 ll0 = {l0, l1}, ll1 = {l2, l3};
    *(__half2*)&g_Axh[0][i]     = hh0; *(__half2*)&g_Axh[0][i + 2] = hh1;
    *(__half2*)&g_Axl[0][i]     = ll0; *(__half2*)&g_Axl[0][i + 2] = ll1;
}

// ---------------- 2) zero recurrent h + barrier slots ----------------
__global__ __launch_bounds__(512) void zero_state() {
    int i = blockIdx.x * blockDim.x + threadIdx.x;
    if (i < 1024) g_sync[i] = 0u;
    ((uint32_t*)g_h16)[i] = 0u;
}

// ---------------- 3) input GEMM: fp16 2-term, BM=128 BN=128 BK=32 ----------------
// 8 warps (4m x 2n), warp tile 32m x 64n. Per k16-slice per warp: 8 LDSM vs 32 HMMA.
#define GM_SA  40
#define GM_AH  0
#define GM_AL  5120
#define GM_WH  10240
#define GM_STG 15360
#define GM_SMEM (2 * GM_STG * 2)

__global__ __launch_bounds__(256, 2) void gemm_mma(int layer)
{
    extern __shared__ __half gsm[];

    int tid = threadIdx.x;
    int wid = tid >> 5;
    int lane = tid & 31;
    int dir = blockIdx.z;
    int n0 = blockIdx.x * 128;
    int m0 = blockIdx.y * 128;

    const __half* Ah = g_Axh[layer == 0 ? 0 : dir];
    const __half* Al = g_Axl[layer == 0 ? 0 : dir];
    const __half* W  = g_Wih16[layer][dir];

    uint32_t sb = smem_u32(gsm);

    int arow0 = tid >> 2, aq = tid & 3;
    auto stage = [&](int buf, int k0) {
        uint32_t base = sb + buf * GM_STG * 2;
#pragma unroll
        for (int i = 0; i < 2; i++) {
            int row = arow0 + i * 64;
            uint32_t d = base + (row * GM_SA + aq * 8) * 2;
            size_t s = (size_t)(m0 + row) * KDIM + k0 + aq * 8;
            cp16(d + GM_AH * 2, Ah + s);
            cp16(d + GM_AL * 2, Al + s);
        }
#pragma unroll
        for (int i = 0; i < 2; i++) {
            int idx = tid + i * 256;
            int row = idx >> 2, q = idx & 3;
            uint32_t d = base + (row * GM_SA + q * 8) * 2 + GM_WH * 2;
            cp16(d, W + (size_t)(n0 + row) * KDIM + k0 + q * 8);
        }
        cp_commit();
    };

    int m0w = (wid >> 1) * 32;
    int n0w = (wid & 1) * 64;
    int a_row = m0w + (lane & 15);
    int a_col = (lane >> 4) * 8;
    int w_n   = n0w + ((lane >> 4) & 1) * 8 + (lane & 7);
    int w_col = ((lane >> 3) & 1) * 8;

    float acc[2][8][4];
#pragma unroll
    for (int mi = 0; mi < 2; mi++)
#pragma unroll
        for (int j = 0; j < 8; j++)
#pragma unroll
            for (int e = 0; e < 4; e++) acc[mi][j][e] = 0.0f;

    stage(0, 0);
    int buf = 0;
#pragma unroll 1
    for (int ch = 0; ch < KDIM / 32; ch++) {
        if (ch < KDIM / 32 - 1) { stage(buf ^ 1, (ch + 1) * 32); cp_wait1(); }
        else                    { cp_wait0(); }
        __syncthreads();
        uint32_t base = sb + buf * GM_STG * 2;
#pragma unroll
        for (int ks = 0; ks < 2; ks++) {
            uint32_t aH[2][4], aL[2][4], wH[4][4];
#pragma unroll
            for (int mi = 0; mi < 2; mi++) {
                uint32_t ao = base + ((a_row + mi * 16) * GM_SA + ks * 16 + a_col) * 2;
                ldsm_x4(aH[mi][0], aH[mi][1], aH[mi][2], aH[mi][3], ao + GM_AH * 2);
                ldsm_x4(aL[mi][0], aL[mi][1], aL[mi][2], aL[mi][3], ao + GM_AL * 2);
            }
#pragma unroll
            for (int jp = 0; jp < 4; jp++) {
                uint32_t wo = base + ((w_n + jp * 16) * GM_SA + ks * 16 + w_col) * 2;
                ldsm_x4(wH[jp][0], wH[jp][1], wH[jp][2], wH[jp][3], wo + GM_WH * 2);
            }
#pragma unroll
            for (int mi = 0; mi < 2; mi++) {
#pragma unroll
                for (int j = 0; j < 8; j++) {
                    int jp = j >> 1, hi = (j & 1) * 2;
                    float* c = acc[mi][j];
                    mma_f16(c[0], c[1], c[2], c[3],
                            aH[mi][0], aH[mi][1], aH[mi][2], aH[mi][3],
                            wH[jp][hi], wH[jp][hi + 1]);
                    mma_f16(c[0], c[1], c[2], c[3],
                            aL[mi][0], aL[mi][1], aL[mi][2], aL[mi][3],
                            wH[jp][hi], wH[jp][hi + 1]);
                }
            }
        }
        __syncthreads();
        buf ^= 1;
    }

    float* C = g_xg[dir];
    int g = lane >> 2, q = lane & 3;
#pragma unroll
    for (int mi = 0; mi < 2; mi++) {
        int row = m0 + m0w + mi * 16 + g;
#pragma unroll
        for (int j = 0; j < 8; j++) {
            int col = n0 + n0w + j * 8 + q * 2;
            float2 v0 = { acc[mi][j][0], acc[mi][j][1] };
            float2 v1 = { acc[mi][j][2], acc[mi][j][3] };
            *(float2*)&C[(size_t)row * G4 + col]       = v0;
            *(float2*)&C[(size_t)(row + 8) * G4 + col] = v1;
        }
    }
}

// ---------------- 4) persistent recurrent kernel: W in regs, pair staging, tree barrier ----
// 128 CTAs x 512 threads (16 warps). dir = cta>>6, jt = cta&63 -> gate cols [jt*64,+64).
// Warp w: k-slice ksl = w>>1 (k in [ksl*128,+128)), n-column nc = w&1 (j in [nc*32,+32)).
// Per step: each warp stages its own 32 rows x 64 halves A sub-slice (8 cp16/lane:
// 32 rows x 8 chunks = 256 = 8 x 32 lanes), pair rendezvous via named bar, sync-free
// MMA with W fragments in registers, 8-slice reduce fused into pointwise,
// 8x8 tree grid barrier per direction (acq_rel chain).
#define RS_A     0
#define RS_ASTR  1032            // A row stride in halves
#define RS_P     66560
#define RS_PSTR  68              // partials row stride in floats
#define RS_PSLC  (32 * RS_PSTR)  // floats per slice (2176)
#define RS_SMEM  (RS_P + 8 * RS_PSLC * 4)   // 136192

__global__ __launch_bounds__(512, 1) void lstm_f16(int layer, float* __restrict__ dout)
{
    extern __shared__ char sm8[];
    uint32_t sb = smem_u32(sm8);
    float* part = (float*)(sm8 + RS_P);

    int tid  = threadIdx.x;
    int wid  = tid >> 5;
    int lane = tid & 31;
    int cta  = blockIdx.x;
    int d    = cta >> 6;
    int jt   = cta & 63;
    int j0g  = jt * 64;
    int hbase = jt * 16;
    int ksl = wid >> 1;          // k slice 0..7
    int nc  = wid & 1;           // n column 0..1

    const __half* WhG = g_Whh16[layer][d];
    const float* xgb = g_xg[d];
    __half* hb = g_h16 + (size_t)d * 2 * BATCH * HID;   // [pp][b][k]

    unsigned* grp_cnt = &g_sync[(d * 8 + (jt >> 3)) * 32];
    unsigned* root_cnt = &g_sync[(16 + d) * 32];
    unsigned* gen = &g_sync[(18 + d) * 32];

    // ---- prologue: W fragments into registers (2 smem staging passes) ----
    uint32_t wf[8][4][2];
#pragma unroll 1
    for (int p = 0; p < 2; p++) {
#pragma unroll
        for (int i = 0; i < 8; i++) {
            int idx = tid + i * 512;
            int r = idx >> 6, g = idx & 63;
            cp16(sb + RS_A + (uint32_t)(r * 1040 + g * 16),
                 WhG + (size_t)(j0g + r) * KDIM + p * 512 + g * 8);
        }
        cp_commit(); cp_wait0(); __syncthreads();
        if ((ksl >> 2) == p) {
            int lk = (ksl & 3) * 128;
#pragma unroll
            for (int ks = 0; ks < 8; ks++)
#pragma unroll
                for (int nt = 0; nt < 4; nt++) {
                    uint32_t addr = sb + RS_A
                        + (uint32_t)((nc * 32 + nt * 8 + (lane & 7)) * 1040
                                     + (lk + ks * 16 + ((lane >> 3) & 1) * 8) * 2);
                    ldsm_x2(wf[ks][nt][0], wf[ks][nt][1], addr);
                }
        }
        __syncthreads();
    }

    uint32_t a_lane = (uint32_t)((lane & 15) * (RS_ASTR * 2) + (lane >> 4) * 16);
    int b  = tid & 31;
    int hl = tid >> 5;            // 0..15 (one hidden index per thread)
    float c_reg = 0.0f;

    int kbase = ksl * 128 + nc * 64;   // this warp's staging k-base (64 halves)

    for (int t = 0; t < SEQ; t++) {
        int time = d ? (SEQ - 1 - t) : t;
        int rp = t & 1, wp = rp ^ 1;
        const __half* hin = hb + (size_t)rp * BATCH * HID;

        // xg prefetch (consumed in pointwise)
        float4 xv = *(const float4*)(xgb + (size_t)time * BATCH * G4
                                     + (size_t)b * G4 + j0g + hl * 4);

        // ---- pair-local staging: this warp stages 32 rows x 64 halves at kbase ----
        // 32 rows x 8 chunks = 256 cp16 per warp -> 8 per lane
#pragma unroll
        for (int i = 0; i < 8; i++) {
            int c = lane + i * 32;
            int r = c >> 3, q = c & 7;
            cp16(sb + RS_A + (uint32_t)(r * (RS_ASTR * 2) + (kbase + q * 8) * 2),
                 hin + (size_t)r * HID + kbase + q * 8);
        }
        cp_commit(); cp_wait0();
        BAR_SYNC(ksl + 1, 64);     // pair rendezvous (membar.cta semantics)

        // ---- MMA pass: no CTA syncs, W in regs ----
        float acc[2][4][4];
#pragma unroll
        for (int mi = 0; mi < 2; mi++)
#pragma unroll
            for (int nt = 0; nt < 4; nt++)
#pragma unroll
                for (int e = 0; e < 4; e++) acc[mi][nt][e] = 0.0f;

        uint32_t ab = sb + RS_A + a_lane + (uint32_t)(ksl * 256);
#pragma unroll
        for (int ks = 0; ks < 8; ks++) {
            uint32_t a0[4], a1[4];
            ldsm_x4(a0[0], a0[1], a0[2], a0[3], ab + ks * 32);
            ldsm_x4(a1[0], a1[1], a1[2], a1[3], ab + 16 * (RS_ASTR * 2) + ks * 32);
#pragma unroll
            for (int nt = 0; nt < 4; nt++) {
                mma_f16(acc[0][nt][0], acc[0][nt][1], acc[0][nt][2], acc[0][nt][3],
                        a0[0], a0[1], a0[2], a0[3], wf[ks][nt][0], wf[ks][nt][1]);
                mma_f16(acc[1][nt][0], acc[1][nt][1], acc[1][nt][2], acc[1][nt][3],
                        a1[0], a1[1], a1[2], a1[3], wf[ks][nt][0], wf[ks][nt][1]);
            }
        }

        // ---- partials -> smem slice ksl ----
        {
            int g = lane >> 2, q = lane & 3;
            float* pbase = part + ksl * RS_PSLC;
#pragma unroll
            for (int mi = 0; mi < 2; mi++)
#pragma unroll
                for (int nt = 0; nt < 4; nt++) {
                    int jj = nc * 32 + nt * 8 + q * 2;
                    float2 v0 = { acc[mi][nt][0], acc[mi][nt][1] };
                    float2 v1 = { acc[mi][nt][2], acc[mi][nt][3] };
                    *(float2*)&pbase[(mi * 16 + g) * RS_PSTR + jj]     = v0;
                    *(float2*)&pbase[(mi * 16 + g + 8) * RS_PSTR + jj] = v1;
                }
        }
        __syncthreads();

        // ---- pointwise: thread owns (b, hl); reduce 8 slices ----
        float gi = xv.x, gf = xv.y, gg = xv.z, go = xv.w;
#pragma unroll
        for (int s = 0; s < 8; s++) {
            float4 v = *(const float4*)&part[s * RS_PSLC + b * RS_PSTR + hl * 4];
            gi += v.x; gf += v.y; gg += v.z; go += v.w;
        }

        float iv = 1.0f / (1.0f + expf(-gi));
        float fv = 1.0f / (1.0f + expf(-gf));
        float gv = tanhf(gg);
        float ov = 1.0f / (1.0f + expf(-go));

        float c = fv * c_reg + iv * gv;
        float hn = ov * tanhf(c);
        c_reg = c;

        int hg = hbase + hl;
        __half hh, hlw;
        split_f16(hn, hh, hlw);
        hb[(size_t)wp * BATCH * HID + (size_t)b * HID + hg] = hh;

        if (layer == 0) {
            size_t arow = ((size_t)time * BATCH + b) * KDIM + hg;
            g_Axh[d][arow] = hh;
            g_Axl[d][arow] = hlw;
        } else {
            dout[(size_t)time * BATCH * 2 * HID + (size_t)b * 2 * HID + d * HID + hg] = hn;
        }
        if (time == SEQ - 1) {
            dout[OUT_HALL + (size_t)layer * BATCH * 2 * HID + (size_t)b * 2 * HID + d * HID + hg] = hn;
            dout[OUT_CALL + (size_t)layer * BATCH * 2 * HID + (size_t)b * 2 * HID + d * HID + hg] = c;
        }

        // ---- 8x8 tree grid barrier per direction ----
        if (t < SEQ - 1) {
            __syncthreads();
            if (tid == 0) {
                unsigned arr = atom_add_acqrel(grp_cnt, 1u);
                if (arr == (unsigned)((t + 1) * 8 - 1)) {
                    unsigned rarr = atom_add_acqrel(root_cnt, 1u);
                    if (rarr == (unsigned)((t + 1) * 8 - 1)) {
                        st_rel(gen, (unsigned)(t + 1));
                    }
                }
                while (ld_acq(gen) < (unsigned)(t + 1)) { }
            }
            __syncthreads();
        }
    }
}

// ---------------- host launcher ----------------
extern "C" void kernel_launch(void* const* d_in, const int* in_sizes, int n_in,
                              void* d_out, int out_size)
{
    const float* x    = (const float*)d_in[0];
    const float* wihf = (const float*)d_in[1];
    const float* whhf = (const float*)d_in[2];
    const float* wihb = (const float*)d_in[3];
    const float* whhb = (const float*)d_in[4];
    float* out = (float*)d_out;
    (void)in_sizes; (void)n_in; (void)out_size;

    cudaFuncSetAttribute(gemm_mma, cudaFuncAttributeMaxDynamicSharedMemorySize, GM_SMEM);
    cudaFuncSetAttribute(lstm_f16, cudaFuncAttributeMaxDynamicSharedMemorySize, RS_SMEM);

    repack_w<<<dim3(G4, 8), 256>>>(wihf, whhf, wihb, whhb);
    conv_x_f16<<<MROWS * KDIM / 1024, 256>>>(x);

    for (int layer = 0; layer < 2; layer++) {
        zero_state<<<128, 512>>>();
        gemm_mma<<<dim3(G4 / 128, MROWS / 128, 2), 256, GM_SMEM>>>(layer);
        lstm_f16<<<NCTA, 512, RS_SMEM>>>(layer, out);
    }
}

// round 14
// speedup vs baseline: 1.1337x; 1.1337x over previous
#include <cuda_runtime.h>
#include <cuda_fp16.h>
#include <math.h>
#include <stdint.h>

// ---------------- problem constants ----------------
#define SEQ   256
#define BATCH 32
#define HID   1024
#define G4    4096
#define KDIM  1024
#define MROWS (SEQ*BATCH)

#define NCTA  128           // persistent grid (2 dirs x 64 j-tiles of 64 gate cols)
#define DCTA  64            // CTAs per direction

// output layout inside d_out (floats)
#define OUT_HALL   (SEQ*BATCH*2*HID)
#define OUT_CALL   (OUT_HALL + 2*BATCH*2*HID)

// ---------------- device scratch ----------------
__device__ float  g_xg  [2][SEQ*BATCH*G4];       // per-direction xg
__device__ __half g_Wih16[2][2][G4*KDIM];        // gate-permuted W_ih fp16 (input GEMM)
__device__ __half g_Whh16[2][2][G4*KDIM];        // gate-permuted W_hh fp16 (recurrence)
__device__ __half g_Axh[2][MROWS*KDIM];          // GEMM A hi ([0]=x layer0, [dir] layer1)
__device__ __half g_Axl[2][MROWS*KDIM];          // GEMM A lo
__device__ __half g_h16[2*2*BATCH*HID];          // [dir][pp][b][k] recurrent h fp16
__device__ unsigned g_sync[64];                  // counter per dir at g_sync[d*32] (128B pad)

// ---------------- sync / async-copy helpers ----------------
__device__ __forceinline__ unsigned ld_acq(const unsigned* p) {
    unsigned v; asm volatile("ld.acquire.gpu.u32 %0, [%1];" : "=r"(v) : "l"(p) : "memory"); return v;
}
__device__ __forceinline__ void red_rel_add(unsigned* p, unsigned v) {
    asm volatile("red.release.gpu.add.u32 [%0], %1;" :: "l"(p), "r"(v) : "memory");
}
__device__ __forceinline__ void cp16(uint32_t s, const void* g) {
    asm volatile("cp.async.cg.shared.global [%0], [%1], 16;" :: "r"(s), "l"(g));
}
__device__ __forceinline__ void cp_commit() { asm volatile("cp.async.commit_group;"); }
__device__ __forceinline__ void cp_wait1()  { asm volatile("cp.async.wait_group 1;" ::: "memory"); }
__device__ __forceinline__ void cp_wait0()  { asm volatile("cp.async.wait_group 0;" ::: "memory"); }

__device__ __forceinline__ uint32_t smem_u32(const void* p) {
    return (uint32_t)__cvta_generic_to_shared(p);
}

// ---------------- mma.sync / ldmatrix helpers (base PTX, sm_80+) ----------------
__device__ __forceinline__ void ldsm_x4(uint32_t& r0, uint32_t& r1, uint32_t& r2, uint32_t& r3,
                                        uint32_t addr) {
    asm volatile("ldmatrix.sync.aligned.m8n8.x4.shared.b16 {%0,%1,%2,%3}, [%4];"
                 : "=r"(r0), "=r"(r1), "=r"(r2), "=r"(r3) : "r"(addr));
}
__device__ __forceinline__ void ldsm_x2(uint32_t& r0, uint32_t& r1, uint32_t addr) {
    asm volatile("ldmatrix.sync.aligned.m8n8.x2.shared.b16 {%0,%1}, [%2];"
                 : "=r"(r0), "=r"(r1) : "r"(addr));
}
__device__ __forceinline__ void mma_f16(float& c0, float& c1, float& c2, float& c3,
                                        uint32_t a0, uint32_t a1, uint32_t a2, uint32_t a3,
                                        uint32_t b0, uint32_t b1) {
    asm volatile("mma.sync.aligned.m16n8k16.row.col.f32.f16.f16.f32 "
                 "{%0,%1,%2,%3}, {%4,%5,%6,%7}, {%8,%9}, {%0,%1,%2,%3};"
                 : "+f"(c0), "+f"(c1), "+f"(c2), "+f"(c3)
                 : "r"(a0), "r"(a1), "r"(a2), "r"(a3), "r"(b0), "r"(b1));
}

// ---------------- split helper ----------------
__device__ __forceinline__ void split_f16(float x, __half& h, __half& l) {
    h = __float2half_rn(x);
    l = __float2half_rn(x - __half2float(h));
}

// ---------------- 1a) weight gate-permute to fp16: row g*H+h -> 4h+g ----------------
__global__ __launch_bounds__(256) void repack_w(
    const float* __restrict__ wihf, const float* __restrict__ whhf,
    const float* __restrict__ wihb, const float* __restrict__ whhb)
{
    int p = blockIdx.x;
    int m = blockIdx.y;
    int dir   = m >> 2;
    int typ   = (m >> 1) & 1;          // 0 = ih, 1 = hh
    int layer = m & 1;
    int srow  = (p & 3) * HID + (p >> 2);

    const float* base = dir ? (typ ? whhb : wihb) : (typ ? whhf : wihf);
    const float* src  = base + (size_t)layer * G4 * KDIM;
    __half* dst = (typ ? g_Whh16[layer][dir] : g_Wih16[layer][dir]) + (size_t)p * KDIM;

    int c = threadIdx.x * 4;
    float4 v = *(const float4*)&src[(size_t)srow * KDIM + c];
    __half2 a = {__float2half_rn(v.x), __float2half_rn(v.y)};
    __half2 b = {__float2half_rn(v.z), __float2half_rn(v.w)};
    *(__half2*)&dst[c]     = a;
    *(__half2*)&dst[c + 2] = b;
}

// ---------------- 1b) fp32 x -> fp16 hi/lo for layer-0 GEMM A ----------------
__global__ __launch_bounds__(256) void conv_x_f16(const float* __restrict__ x)
{
    size_t i = ((size_t)blockIdx.x * 256 + threadIdx.x) * 4;
    float4 v = *(const float4*)&x[i];
    __half h0, l0, h1, l1, h2, l2, h3, l3;
    split_f16(v.x, h0, l0); split_f16(v.y, h1, l1);
    split_f16(v.z, h2, l2); split_f16(v.w, h3, l3);
    __half2 hh0 = {h0, h1}, hh1 = {h2, h3};
    __half2 ll0 = {l0, l1}, ll1 = {l2, l3};
    *(__half2*)&g_Axh[0][i]     = hh0; *(__half2*)&g_Axh[0][i + 2] = hh1;
    *(__half2*)&g_Axl[0][i]     = ll0; *(__half2*)&g_Axl[0][i + 2] = ll1;
}

// ---------------- 2) zero recurrent h + barrier counters ----------------
__global__ __launch_bounds__(512) void zero_state() {
    int i = blockIdx.x * blockDim.x + threadIdx.x;
    if (i < 64) g_sync[i] = 0u;
    ((uint32_t*)g_h16)[i] = 0u;
}

// ---------------- 3) input GEMM: fp16 2-term, BM=128 BN=128 BK=32, 3-stage ----------------
// 8 warps (4m x 2n), warp tile 32m x 64n. ONE __syncthreads per chunk:
// iter ch: [wait buf ch][sync][stage buf ch+2][compute buf ch].
// Staging buffer (ch+2)%3 == (ch-1)%3 is safe: the sync separates it from all
// warps' compute(ch-1) reads of that buffer.
#define GM_SA  40
#define GM_AH  0
#define GM_AL  5120
#define GM_WH  10240
#define GM_STG 15360
#define GM_SMEM (3 * GM_STG * 2)

__global__ __launch_bounds__(256, 2) void gemm_mma(int layer)
{
    extern __shared__ __half gsm[];

    int tid = threadIdx.x;
    int wid = tid >> 5;
    int lane = tid & 31;
    int dir = blockIdx.z;
    int n0 = blockIdx.x * 128;
    int m0 = blockIdx.y * 128;

    const __half* Ah = g_Axh[layer == 0 ? 0 : dir];
    const __half* Al = g_Axl[layer == 0 ? 0 : dir];
    const __half* W  = g_Wih16[layer][dir];

    uint32_t sb = smem_u32(gsm);

    int arow0 = tid >> 2, aq = tid & 3;
    auto stage = [&](int buf, int k0) {
        uint32_t base = sb + buf * GM_STG * 2;
#pragma unroll
        for (int i = 0; i < 2; i++) {
            int row = arow0 + i * 64;
            uint32_t d = base + (row * GM_SA + aq * 8) * 2;
            size_t s = (size_t)(m0 + row) * KDIM + k0 + aq * 8;
            cp16(d + GM_AH * 2, Ah + s);
            cp16(d + GM_AL * 2, Al + s);
        }
#pragma unroll
        for (int i = 0; i < 2; i++) {
            int idx = tid + i * 256;
            int row = idx >> 2, q = idx & 3;
            uint32_t d = base + (row * GM_SA + q * 8) * 2 + GM_WH * 2;
            cp16(d, W + (size_t)(n0 + row) * KDIM + k0 + q * 8);
        }
        cp_commit();
    };

    int m0w = (wid >> 1) * 32;
    int n0w = (wid & 1) * 64;
    int a_row = m0w + (lane & 15);
    int a_col = (lane >> 4) * 8;
    int w_n   = n0w + ((lane >> 4) & 1) * 8 + (lane & 7);
    int w_col = ((lane >> 3) & 1) * 8;

    float acc[2][8][4];
#pragma unroll
    for (int mi = 0; mi < 2; mi++)
#pragma unroll
        for (int j = 0; j < 8; j++)
#pragma unroll
            for (int e = 0; e < 4; e++) acc[mi][j][e] = 0.0f;

    stage(0, 0);
    stage(1, 32);
#pragma unroll 1
    for (int ch = 0; ch < KDIM / 32; ch++) {
        int buf = ch % 3;
        if (ch < KDIM / 32 - 1) cp_wait1(); else cp_wait0();
        __syncthreads();
        if (ch + 2 < KDIM / 32) stage((ch + 2) % 3, (ch + 2) * 32);

        uint32_t base = sb + buf * GM_STG * 2;
#pragma unroll
        for (int ks = 0; ks < 2; ks++) {
            uint32_t aH[2][4], aL[2][4], wH[4][4];
#pragma unroll
            for (int mi = 0; mi < 2; mi++) {
                uint32_t ao = base + ((a_row + mi * 16) * GM_SA + ks * 16 + a_col) * 2;
                ldsm_x4(aH[mi][0], aH[mi][1], aH[mi][2], aH[mi][3], ao + GM_AH * 2);
                ldsm_x4(aL[mi][0], aL[mi][1], aL[mi][2], aL[mi][3], ao + GM_AL * 2);
            }
#pragma unroll
            for (int jp = 0; jp < 4; jp++) {
                uint32_t wo = base + ((w_n + jp * 16) * GM_SA + ks * 16 + w_col) * 2;
                ldsm_x4(wH[jp][0], wH[jp][1], wH[jp][2], wH[jp][3], wo + GM_WH * 2);
            }
#pragma unroll
            for (int mi = 0; mi < 2; mi++) {
#pragma unroll
                for (int j = 0; j < 8; j++) {
                    int jp = j >> 1, hi = (j & 1) * 2;
                    float* c = acc[mi][j];
                    mma_f16(c[0], c[1], c[2], c[3],
                            aH[mi][0], aH[mi][1], aH[mi][2], aH[mi][3],
                            wH[jp][hi], wH[jp][hi + 1]);
                    mma_f16(c[0], c[1], c[2], c[3],
                            aL[mi][0], aL[mi][1], aL[mi][2], aL[mi][3],
                            wH[jp][hi], wH[jp][hi + 1]);
                }
            }
        }
    }

    float* C = g_xg[dir];
    int g = lane >> 2, q = lane & 3;
#pragma unroll
    for (int mi = 0; mi < 2; mi++) {
        int row = m0 + m0w + mi * 16 + g;
#pragma unroll
        for (int j = 0; j < 8; j++) {
            int col = n0 + n0w + j * 8 + q * 2;
            float2 v0 = { acc[mi][j][0], acc[mi][j][1] };
            float2 v1 = { acc[mi][j][2], acc[mi][j][3] };
            *(float2*)&C[(size_t)row * G4 + col]       = v0;
            *(float2*)&C[(size_t)(row + 8) * G4 + col] = v1;
        }
    }
}

// ---------------- 4) persistent recurrent kernel (R11 structure, red+poll barrier) ----------
// 128 CTAs x 512 threads (16 warps). dir = cta>>6, jt = cta&63 -> gate cols [jt*64,+64).
// Warp w: k-slice ksl = w>>1 (k in [ksl*128,+128)), n-column nc = w&1 (j in [nc*32,+32)).
// W fragments in registers (loaded once per layer). Per step: CTA-wide h stage (64KB),
// sync-free MMA pass, 8-slice reduce fused into pointwise, red.release counter barrier.
#define RS_A     0
#define RS_ASTR  1032            // A row stride in halves
#define RS_P     66560
#define RS_PSTR  68              // partials row stride in floats
#define RS_PSLC  (32 * RS_PSTR)  // floats per slice (2176)
#define RS_SMEM  (RS_P + 8 * RS_PSLC * 4)   // 136192

__global__ __launch_bounds__(512, 1) void lstm_f16(int layer, float* __restrict__ dout)
{
    extern __shared__ char sm8[];
    uint32_t sb = smem_u32(sm8);
    float* part = (float*)(sm8 + RS_P);

    int tid  = threadIdx.x;
    int wid  = tid >> 5;
    int lane = tid & 31;
    int cta  = blockIdx.x;
    int d    = cta >> 6;
    int jt   = cta & 63;
    int j0g  = jt * 64;
    int hbase = jt * 16;
    int ksl = wid >> 1;          // k slice 0..7
    int nc  = wid & 1;           // n column 0..1

    const __half* WhG = g_Whh16[layer][d];
    const float* xgb = g_xg[d];
    __half* hb = g_h16 + (size_t)d * 2 * BATCH * HID;   // [pp][b][k]

    unsigned* cnt = &g_sync[d * 32];

    // ---- prologue: W fragments into registers (2 smem staging passes) ----
    uint32_t wf[8][4][2];
#pragma unroll 1
    for (int p = 0; p < 2; p++) {
#pragma unroll
        for (int i = 0; i < 8; i++) {
            int idx = tid + i * 512;
            int r = idx >> 6, g = idx & 63;
            cp16(sb + RS_A + (uint32_t)(r * 1040 + g * 16),
                 WhG + (size_t)(j0g + r) * KDIM + p * 512 + g * 8);
        }
        cp_commit(); cp_wait0(); __syncthreads();
        if ((ksl >> 2) == p) {
            int lk = (ksl & 3) * 128;
#pragma unroll
            for (int ks = 0; ks < 8; ks++)
#pragma unroll
                for (int nt = 0; nt < 4; nt++) {
                    uint32_t addr = sb + RS_A
                        + (uint32_t)((nc * 32 + nt * 8 + (lane & 7)) * 1040
                                     + (lk + ks * 16 + ((lane >> 3) & 1) * 8) * 2);
                    ldsm_x2(wf[ks][nt][0], wf[ks][nt][1], addr);
                }
        }
        __syncthreads();
    }

    uint32_t a_lane = (uint32_t)((lane & 15) * (RS_ASTR * 2) + (lane >> 4) * 16);
    int b  = tid & 31;
    int hl = tid >> 5;            // 0..15 (one hidden index per thread)
    float c_reg = 0.0f;

    for (int t = 0; t < SEQ; t++) {
        int time = d ? (SEQ - 1 - t) : t;
        int rp = t & 1, wp = rp ^ 1;
        const __half* hin = hb + (size_t)rp * BATCH * HID;

        // xg prefetch (consumed in pointwise)
        float4 xv = *(const float4*)(xgb + (size_t)time * BATCH * G4
                                     + (size_t)b * G4 + j0g + hl * 4);

        // ---- stage full h tile: 32 rows x 1024 halves ----
#pragma unroll
        for (int i = 0; i < 8; i++) {
            int idx = tid + i * 512;
            int r = idx >> 7, g = idx & 127;
            cp16(sb + RS_A + (uint32_t)(r * (RS_ASTR * 2) + g * 16),
                 hin + (size_t)r * HID + g * 8);
        }
        cp_commit(); cp_wait0(); __syncthreads();

        // ---- MMA pass: no syncs, W in regs ----
        float acc[2][4][4];
#pragma unroll
        for (int mi = 0; mi < 2; mi++)
#pragma unroll
            for (int nt = 0; nt < 4; nt++)
#pragma unroll
                for (int e = 0; e < 4; e++) acc[mi][nt][e] = 0.0f;

        uint32_t ab = sb + RS_A + a_lane + (uint32_t)(ksl * 256);
#pragma unroll
        for (int ks = 0; ks < 8; ks++) {
            uint32_t a0[4], a1[4];
            ldsm_x4(a0[0], a0[1], a0[2], a0[3], ab + ks * 32);
            ldsm_x4(a1[0], a1[1], a1[2], a1[3], ab + 16 * (RS_ASTR * 2) + ks * 32);
#pragma unroll
            for (int nt = 0; nt < 4; nt++) {
                mma_f16(acc[0][nt][0], acc[0][nt][1], acc[0][nt][2], acc[0][nt][3],
                        a0[0], a0[1], a0[2], a0[3], wf[ks][nt][0], wf[ks][nt][1]);
                mma_f16(acc[1][nt][0], acc[1][nt][1], acc[1][nt][2], acc[1][nt][3],
                        a1[0], a1[1], a1[2], a1[3], wf[ks][nt][0], wf[ks][nt][1]);
            }
        }

        // ---- partials -> smem slice ksl ----
        {
            int g = lane >> 2, q = lane & 3;
            float* pbase = part + ksl * RS_PSLC;
#pragma unroll
            for (int mi = 0; mi < 2; mi++)
#pragma unroll
                for (int nt = 0; nt < 4; nt++) {
                    int jj = nc * 32 + nt * 8 + q * 2;
                    float2 v0 = { acc[mi][nt][0], acc[mi][nt][1] };
                    float2 v1 = { acc[mi][nt][2], acc[mi][nt][3] };
                    *(float2*)&pbase[(mi * 16 + g) * RS_PSTR + jj]     = v0;
                    *(float2*)&pbase[(mi * 16 + g + 8) * RS_PSTR + jj] = v1;
                }
        }
        __syncthreads();

        // ---- pointwise: thread owns (b, hl); reduce 8 slices ----
        float gi = xv.x, gf = xv.y, gg = xv.z, go = xv.w;
#pragma unroll
        for (int s = 0; s < 8; s++) {
            float4 v = *(const float4*)&part[s * RS_PSLC + b * RS_PSTR + hl * 4];
            gi += v.x; gf += v.y; gg += v.z; go += v.w;
        }

        float iv = 1.0f / (1.0f + expf(-gi));
        float fv = 1.0f / (1.0f + expf(-gf));
        float gv = tanhf(gg);
        float ov = 1.0f / (1.0f + expf(-go));

        float c = fv * c_reg + iv * gv;
        float hn = ov * tanhf(c);
        c_reg = c;

        int hg = hbase + hl;
        __half hh, hlw;
        split_f16(hn, hh, hlw);
        hb[(size_t)wp * BATCH * HID + (size_t)b * HID + hg] = hh;

        if (layer == 0) {
            size_t arow = ((size_t)time * BATCH + b) * KDIM + hg;
            g_Axh[d][arow] = hh;
            g_Axl[d][arow] = hlw;
        } else {
            dout[(size_t)time * BATCH * 2 * HID + (size_t)b * 2 * HID + d * HID + hg] = hn;
        }
        if (time == SEQ - 1) {
            dout[OUT_HALL + (size_t)layer * BATCH * 2 * HID + (size_t)b * 2 * HID + d * HID + hg] = hn;
            dout[OUT_CALL + (size_t)layer * BATCH * 2 * HID + (size_t)b * 2 * HID + d * HID + hg] = c;
        }

        // ---- per-direction counter barrier: release-red arrive, acquire poll ----
        if (t < SEQ - 1) {
            __syncthreads();
            if (tid == 0) {
                red_rel_add(cnt, 1u);
                unsigned target = (unsigned)((t + 1) * DCTA);
                while (ld_acq(cnt) < target) { }
            }
            __syncthreads();
        }
    }
}

// ---------------- host launcher ----------------
extern "C" void kernel_launch(void* const* d_in, const int* in_sizes, int n_in,
                              void* d_out, int out_size)
{
    const float* x    = (const float*)d_in[0];
    const float* wihf = (const float*)d_in[1];
    const float* whhf = (const float*)d_in[2];
    const float* wihb = (const float*)d_in[3];
    const float* whhb = (const float*)d_in[4];
    float* out = (float*)d_out;
    (void)in_sizes; (void)n_in; (void)out_size;

    cudaFuncSetAttribute(gemm_mma, cudaFuncAttributeMaxDynamicSharedMemorySize, GM_SMEM);
    cudaFuncSetAttribute(lstm_f16, cudaFuncAttributeMaxDynamicSharedMemorySize, RS_SMEM);

    repack_w<<<dim3(G4, 8), 256>>>(wihf, whhf, wihb, whhb);
    conv_x_f16<<<MROWS * KDIM / 1024, 256>>>(x);

    for (int layer = 0; layer < 2; layer++) {
        zero_state<<<128, 512>>>();
        gemm_mma<<<dim3(G4 / 128, MROWS / 128, 2), 256, GM_SMEM>>>(layer);
        lstm_f16<<<NCTA, 512, RS_SMEM>>>(layer, out);
    }
}

// round 15
// speedup vs baseline: 1.1469x; 1.0116x over previous
#include <cuda_runtime.h>
#include <cuda_fp16.h>
#include <math.h>
#include <stdint.h>

// ---------------- problem constants ----------------
#define SEQ   256
#define BATCH 32
#define HID   1024
#define G4    4096
#define KDIM  1024
#define MROWS (SEQ*BATCH)

#define NCTA  128           // persistent grid (2 dirs x 64 j-tiles of 64 gate cols)
#define DCTA  64            // CTAs per direction

// output layout inside d_out (floats)
#define OUT_HALL   (SEQ*BATCH*2*HID)
#define OUT_CALL   (OUT_HALL + 2*BATCH*2*HID)

// ---------------- device scratch ----------------
__device__ float  g_xg  [2][SEQ*BATCH*G4];       // per-direction xg
__device__ __half g_Wih16[2][2][G4*KDIM];        // gate-permuted W_ih fp16 (input GEMM)
__device__ __half g_Whh16[2][2][G4*KDIM];        // gate-permuted W_hh fp16 (recurrence)
__device__ __half g_Axh[2][MROWS*KDIM];          // GEMM A hi ([0]=x layer0, [dir] layer1)
__device__ __half g_Axl[2][MROWS*KDIM];          // GEMM A lo
__device__ __half g_h16[2*2*BATCH*HID];          // [dir][pp][b][k] recurrent h fp16
__device__ unsigned g_sync[64];                  // counter per dir at g_sync[d*32] (128B pad)

// ---------------- sync / async-copy helpers ----------------
__device__ __forceinline__ unsigned ld_acq(const unsigned* p) {
    unsigned v; asm volatile("ld.acquire.gpu.u32 %0, [%1];" : "=r"(v) : "l"(p) : "memory"); return v;
}
__device__ __forceinline__ void red_rel_add(unsigned* p, unsigned v) {
    asm volatile("red.release.gpu.add.u32 [%0], %1;" :: "l"(p), "r"(v) : "memory");
}
__device__ __forceinline__ void cp16(uint32_t s, const void* g) {
    asm volatile("cp.async.cg.shared.global [%0], [%1], 16;" :: "r"(s), "l"(g));
}
__device__ __forceinline__ void cp_commit() { asm volatile("cp.async.commit_group;"); }
__device__ __forceinline__ void cp_wait1()  { asm volatile("cp.async.wait_group 1;" ::: "memory"); }
__device__ __forceinline__ void cp_wait0()  { asm volatile("cp.async.wait_group 0;" ::: "memory"); }

__device__ __forceinline__ uint32_t smem_u32(const void* p) {
    return (uint32_t)__cvta_generic_to_shared(p);
}

// ---------------- mma.sync / ldmatrix helpers (base PTX, sm_80+) ----------------
__device__ __forceinline__ void ldsm_x4(uint32_t& r0, uint32_t& r1, uint32_t& r2, uint32_t& r3,
                                        uint32_t addr) {
    asm volatile("ldmatrix.sync.aligned.m8n8.x4.shared.b16 {%0,%1,%2,%3}, [%4];"
                 : "=r"(r0), "=r"(r1), "=r"(r2), "=r"(r3) : "r"(addr));
}
__device__ __forceinline__ void ldsm_x2(uint32_t& r0, uint32_t& r1, uint32_t addr) {
    asm volatile("ldmatrix.sync.aligned.m8n8.x2.shared.b16 {%0,%1}, [%2];"
                 : "=r"(r0), "=r"(r1) : "r"(addr));
}
__device__ __forceinline__ void mma_f16(float& c0, float& c1, float& c2, float& c3,
                                        uint32_t a0, uint32_t a1, uint32_t a2, uint32_t a3,
                                        uint32_t b0, uint32_t b1) {
    asm volatile("mma.sync.aligned.m16n8k16.row.col.f32.f16.f16.f32 "
                 "{%0,%1,%2,%3}, {%4,%5,%6,%7}, {%8,%9}, {%0,%1,%2,%3};"
                 : "+f"(c0), "+f"(c1), "+f"(c2), "+f"(c3)
                 : "r"(a0), "r"(a1), "r"(a2), "r"(a3), "r"(b0), "r"(b1));
}

// ---------------- split helper ----------------
__device__ __forceinline__ void split_f16(float x, __half& h, __half& l) {
    h = __float2half_rn(x);
    l = __float2half_rn(x - __half2float(h));
}

// ---------------- 1a) weight gate-permute to fp16: row g*H+h -> 4h+g ----------------
__global__ __launch_bounds__(256) void repack_w(
    const float* __restrict__ wihf, const float* __restrict__ whhf,
    const float* __restrict__ wihb, const float* __restrict__ whhb)
{
    int p = blockIdx.x;
    int m = blockIdx.y;
    int dir   = m >> 2;
    int typ   = (m >> 1) & 1;          // 0 = ih, 1 = hh
    int layer = m & 1;
    int srow  = (p & 3) * HID + (p >> 2);

    const float* base = dir ? (typ ? whhb : wihb) : (typ ? whhf : wihf);
    const float* src  = base + (size_t)layer * G4 * KDIM;
    __half* dst = (typ ? g_Whh16[layer][dir] : g_Wih16[layer][dir]) + (size_t)p * KDIM;

    int c = threadIdx.x * 4;
    float4 v = *(const float4*)&src[(size_t)srow * KDIM + c];
    __half2 a = {__float2half_rn(v.x), __float2half_rn(v.y)};
    __half2 b = {__float2half_rn(v.z), __float2half_rn(v.w)};
    *(__half2*)&dst[c]     = a;
    *(__half2*)&dst[c + 2] = b;
}

// ---------------- 1b) fp32 x -> fp16 hi/lo for layer-0 GEMM A ----------------
__global__ __launch_bounds__(256) void conv_x_f16(const float* __restrict__ x)
{
    size_t i = ((size_t)blockIdx.x * 256 + threadIdx.x) * 4;
    float4 v = *(const float4*)&x[i];
    __half h0, l0, h1, l1, h2, l2, h3, l3;
    split_f16(v.x, h0, l0); split_f16(v.y, h1, l1);
    split_f16(v.z, h2, l2); split_f16(v.w, h3, l3);
    __half2 hh0 = {h0, h1}, hh1 = {h2, h3};
    __half2 ll0 = {l0, l1}, ll1 = {l2, l3};
    *(__half2*)&g_Axh[0][i]     = hh0; *(__half2*)&g_Axh[0][i + 2] = hh1;
    *(__half2*)&g_Axl[0][i]     = ll0; *(__half2*)&g_Axl[0][i + 2] = ll1;
}

// ---------------- 2) zero recurrent h + barrier counters ----------------
__global__ __launch_bounds__(512) void zero_state() {
    int i = blockIdx.x * blockDim.x + threadIdx.x;
    if (i < 64) g_sync[i] = 0u;
    ((uint32_t*)g_h16)[i] = 0u;
}

// ---------------- 3) input GEMM: fp16 2-term, BM=128 BN=128 BK=32 (R11 2-stage) --------
// 8 warps (4m x 2n), warp tile 32m x 64n. Stage(ch+1) issued BEFORE cp_wait1 so the
// prefetch stays a full chunk ahead (this ordering measured fastest: 706us, tensor 64%).
#define GM_SA  40
#define GM_AH  0
#define GM_AL  5120
#define GM_WH  10240
#define GM_STG 15360
#define GM_SMEM (2 * GM_STG * 2)

__global__ __launch_bounds__(256, 2) void gemm_mma(int layer)
{
    extern __shared__ __half gsm[];

    int tid = threadIdx.x;
    int wid = tid >> 5;
    int lane = tid & 31;
    int dir = blockIdx.z;
    int n0 = blockIdx.x * 128;
    int m0 = blockIdx.y * 128;

    const __half* Ah = g_Axh[layer == 0 ? 0 : dir];
    const __half* Al = g_Axl[layer == 0 ? 0 : dir];
    const __half* W  = g_Wih16[layer][dir];

    uint32_t sb = smem_u32(gsm);

    int arow0 = tid >> 2, aq = tid & 3;
    auto stage = [&](int buf, int k0) {
        uint32_t base = sb + buf * GM_STG * 2;
#pragma unroll
        for (int i = 0; i < 2; i++) {
            int row = arow0 + i * 64;
            uint32_t d = base + (row * GM_SA + aq * 8) * 2;
            size_t s = (size_t)(m0 + row) * KDIM + k0 + aq * 8;
            cp16(d + GM_AH * 2, Ah + s);
            cp16(d + GM_AL * 2, Al + s);
        }
#pragma unroll
        for (int i = 0; i < 2; i++) {
            int idx = tid + i * 256;
            int row = idx >> 2, q = idx & 3;
            uint32_t d = base + (row * GM_SA + q * 8) * 2 + GM_WH * 2;
            cp16(d, W + (size_t)(n0 + row) * KDIM + k0 + q * 8);
        }
        cp_commit();
    };

    int m0w = (wid >> 1) * 32;
    int n0w = (wid & 1) * 64;
    int a_row = m0w + (lane & 15);
    int a_col = (lane >> 4) * 8;
    int w_n   = n0w + ((lane >> 4) & 1) * 8 + (lane & 7);
    int w_col = ((lane >> 3) & 1) * 8;

    float acc[2][8][4];
#pragma unroll
    for (int mi = 0; mi < 2; mi++)
#pragma unroll
        for (int j = 0; j < 8; j++)
#pragma unroll
            for (int e = 0; e < 4; e++) acc[mi][j][e] = 0.0f;

    stage(0, 0);
    int buf = 0;
#pragma unroll 1
    for (int ch = 0; ch < KDIM / 32; ch++) {
        if (ch < KDIM / 32 - 1) { stage(buf ^ 1, (ch + 1) * 32); cp_wait1(); }
        else                    { cp_wait0(); }
        __syncthreads();
        uint32_t base = sb + buf * GM_STG * 2;
#pragma unroll
        for (int ks = 0; ks < 2; ks++) {
            uint32_t aH[2][4], aL[2][4], wH[4][4];
#pragma unroll
            for (int mi = 0; mi < 2; mi++) {
                uint32_t ao = base + ((a_row + mi * 16) * GM_SA + ks * 16 + a_col) * 2;
                ldsm_x4(aH[mi][0], aH[mi][1], aH[mi][2], aH[mi][3], ao + GM_AH * 2);
                ldsm_x4(aL[mi][0], aL[mi][1], aL[mi][2], aL[mi][3], ao + GM_AL * 2);
            }
#pragma unroll
            for (int jp = 0; jp < 4; jp++) {
                uint32_t wo = base + ((w_n + jp * 16) * GM_SA + ks * 16 + w_col) * 2;
                ldsm_x4(wH[jp][0], wH[jp][1], wH[jp][2], wH[jp][3], wo + GM_WH * 2);
            }
#pragma unroll
            for (int mi = 0; mi < 2; mi++) {
#pragma unroll
                for (int j = 0; j < 8; j++) {
                    int jp = j >> 1, hi = (j & 1) * 2;
                    float* c = acc[mi][j];
                    mma_f16(c[0], c[1], c[2], c[3],
                            aH[mi][0], aH[mi][1], aH[mi][2], aH[mi][3],
                            wH[jp][hi], wH[jp][hi + 1]);
                    mma_f16(c[0], c[1], c[2], c[3],
                            aL[mi][0], aL[mi][1], aL[mi][2], aL[mi][3],
                            wH[jp][hi], wH[jp][hi + 1]);
                }
            }
        }
        __syncthreads();
        buf ^= 1;
    }

    float* C = g_xg[dir];
    int g = lane >> 2, q = lane & 3;
#pragma unroll
    for (int mi = 0; mi < 2; mi++) {
        int row = m0 + m0w + mi * 16 + g;
#pragma unroll
        for (int j = 0; j < 8; j++) {
            int col = n0 + n0w + j * 8 + q * 2;
            float2 v0 = { acc[mi][j][0], acc[mi][j][1] };
            float2 v1 = { acc[mi][j][2], acc[mi][j][3] };
            *(float2*)&C[(size_t)row * G4 + col]       = v0;
            *(float2*)&C[(size_t)(row + 8) * G4 + col] = v1;
        }
    }
}

// ---------------- 4) persistent recurrent kernel (R14: W in regs, red+poll barrier) ------
// 128 CTAs x 512 threads (16 warps). dir = cta>>6, jt = cta&63 -> gate cols [jt*64,+64).
// Warp w: k-slice ksl = w>>1 (k in [ksl*128,+128)), n-column nc = w&1 (j in [nc*32,+32)).
// W fragments in registers (loaded once per layer). Per step: CTA-wide h stage (64KB),
// sync-free MMA pass, 8-slice reduce fused into pointwise, red.release counter barrier.
#define RS_A     0
#define RS_ASTR  1032            // A row stride in halves
#define RS_P     66560
#define RS_PSTR  68              // partials row stride in floats
#define RS_PSLC  (32 * RS_PSTR)  // floats per slice (2176)
#define RS_SMEM  (RS_P + 8 * RS_PSLC * 4)   // 136192

__global__ __launch_bounds__(512, 1) void lstm_f16(int layer, float* __restrict__ dout)
{
    extern __shared__ char sm8[];
    uint32_t sb = smem_u32(sm8);
    float* part = (float*)(sm8 + RS_P);

    int tid  = threadIdx.x;
    int wid  = tid >> 5;
    int lane = tid & 31;
    int cta  = blockIdx.x;
    int d    = cta >> 6;
    int jt   = cta & 63;
    int j0g  = jt * 64;
    int hbase = jt * 16;
    int ksl = wid >> 1;          // k slice 0..7
    int nc  = wid & 1;           // n column 0..1

    const __half* WhG = g_Whh16[layer][d];
    const float* xgb = g_xg[d];
    __half* hb = g_h16 + (size_t)d * 2 * BATCH * HID;   // [pp][b][k]

    unsigned* cnt = &g_sync[d * 32];

    // ---- prologue: W fragments into registers (2 smem staging passes) ----
    uint32_t wf[8][4][2];
#pragma unroll 1
    for (int p = 0; p < 2; p++) {
#pragma unroll
        for (int i = 0; i < 8; i++) {
            int idx = tid + i * 512;
            int r = idx >> 6, g = idx & 63;
            cp16(sb + RS_A + (uint32_t)(r * 1040 + g * 16),
                 WhG + (size_t)(j0g + r) * KDIM + p * 512 + g * 8);
        }
        cp_commit(); cp_wait0(); __syncthreads();
        if ((ksl >> 2) == p) {
            int lk = (ksl & 3) * 128;
#pragma unroll
            for (int ks = 0; ks < 8; ks++)
#pragma unroll
                for (int nt = 0; nt < 4; nt++) {
                    uint32_t addr = sb + RS_A
                        + (uint32_t)((nc * 32 + nt * 8 + (lane & 7)) * 1040
                                     + (lk + ks * 16 + ((lane >> 3) & 1) * 8) * 2);
                    ldsm_x2(wf[ks][nt][0], wf[ks][nt][1], addr);
                }
        }
        __syncthreads();
    }

    uint32_t a_lane = (uint32_t)((lane & 15) * (RS_ASTR * 2) + (lane >> 4) * 16);
    int b  = tid & 31;
    int hl = tid >> 5;            // 0..15 (one hidden index per thread)
    float c_reg = 0.0f;

    for (int t = 0; t < SEQ; t++) {
        int time = d ? (SEQ - 1 - t) : t;
        int rp = t & 1, wp = rp ^ 1;
        const __half* hin = hb + (size_t)rp * BATCH * HID;

        // xg prefetch (consumed in pointwise)
        float4 xv = *(const float4*)(xgb + (size_t)time * BATCH * G4
                                     + (size_t)b * G4 + j0g + hl * 4);

        // ---- stage full h tile: 32 rows x 1024 halves ----
#pragma unroll
        for (int i = 0; i < 8; i++) {
            int idx = tid + i * 512;
            int r = idx >> 7, g = idx & 127;
            cp16(sb + RS_A + (uint32_t)(r * (RS_ASTR * 2) + g * 16),
                 hin + (size_t)r * HID + g * 8);
        }
        cp_commit(); cp_wait0(); __syncthreads();

        // ---- MMA pass: no syncs, W in regs ----
        float acc[2][4][4];
#pragma unroll
        for (int mi = 0; mi < 2; mi++)
#pragma unroll
            for (int nt = 0; nt < 4; nt++)
#pragma unroll
                for (int e = 0; e < 4; e++) acc[mi][nt][e] = 0.0f;

        uint32_t ab = sb + RS_A + a_lane + (uint32_t)(ksl * 256);
#pragma unroll
        for (int ks = 0; ks < 8; ks++) {
            uint32_t a0[4], a1[4];
            ldsm_x4(a0[0], a0[1], a0[2], a0[3], ab + ks * 32);
            ldsm_x4(a1[0], a1[1], a1[2], a1[3], ab + 16 * (RS_ASTR * 2) + ks * 32);
#pragma unroll
            for (int nt = 0; nt < 4; nt++) {
                mma_f16(acc[0][nt][0], acc[0][nt][1], acc[0][nt][2], acc[0][nt][3],
                        a0[0], a0[1], a0[2], a0[3], wf[ks][nt][0], wf[ks][nt][1]);
                mma_f16(acc[1][nt][0], acc[1][nt][1], acc[1][nt][2], acc[1][nt][3],
                        a1[0], a1[1], a1[2], a1[3], wf[ks][nt][0], wf[ks][nt][1]);
            }
        }

        // ---- partials -> smem slice ksl ----
        {
            int g = lane >> 2, q = lane & 3;
            float* pbase = part + ksl * RS_PSLC;
#pragma unroll
            for (int mi = 0; mi < 2; mi++)
#pragma unroll
                for (int nt = 0; nt < 4; nt++) {
                    int jj = nc * 32 + nt * 8 + q * 2;
                    float2 v0 = { acc[mi][nt][0], acc[mi][nt][1] };
                    float2 v1 = { acc[mi][nt][2], acc[mi][nt][3] };
                    *(float2*)&pbase[(mi * 16 + g) * RS_PSTR + jj]     = v0;
                    *(float2*)&pbase[(mi * 16 + g + 8) * RS_PSTR + jj] = v1;
                }
        }
        __syncthreads();

        // ---- pointwise: thread owns (b, hl); reduce 8 slices ----
        float gi = xv.x, gf = xv.y, gg = xv.z, go = xv.w;
#pragma unroll
        for (int s = 0; s < 8; s++) {
            float4 v = *(const float4*)&part[s * RS_PSLC + b * RS_PSTR + hl * 4];
            gi += v.x; gf += v.y; gg += v.z; go += v.w;
        }

        float iv = 1.0f / (1.0f + expf(-gi));
        float fv = 1.0f / (1.0f + expf(-gf));
        float gv = tanhf(gg);
        float ov = 1.0f / (1.0f + expf(-go));

        float c = fv * c_reg + iv * gv;
        float hn = ov * tanhf(c);
        c_reg = c;

        int hg = hbase + hl;
        __half hh, hlw;
        split_f16(hn, hh, hlw);
        hb[(size_t)wp * BATCH * HID + (size_t)b * HID + hg] = hh;

        if (layer == 0) {
            size_t arow = ((size_t)time * BATCH + b) * KDIM + hg;
            g_Axh[d][arow] = hh;
            g_Axl[d][arow] = hlw;
        } else {
            dout[(size_t)time * BATCH * 2 * HID + (size_t)b * 2 * HID + d * HID + hg] = hn;
        }
        if (time == SEQ - 1) {
            dout[OUT_HALL + (size_t)layer * BATCH * 2 * HID + (size_t)b * 2 * HID + d * HID + hg] = hn;
            dout[OUT_CALL + (size_t)layer * BATCH * 2 * HID + (size_t)b * 2 * HID + d * HID + hg] = c;
        }

        // ---- per-direction counter barrier: release-red arrive, acquire poll ----
        if (t < SEQ - 1) {
            __syncthreads();
            if (tid == 0) {
                red_rel_add(cnt, 1u);
                unsigned target = (unsigned)((t + 1) * DCTA);
                while (ld_acq(cnt) < target) { }
            }
            __syncthreads();
        }
    }
}

// ---------------- host launcher ----------------
extern "C" void kernel_launch(void* const* d_in, const int* in_sizes, int n_in,
                              void* d_out, int out_size)
{
    const float* x    = (const float*)d_in[0];
    const float* wihf = (const float*)d_in[1];
    const float* whhf = (const float*)d_in[2];
    const float* wihb = (const float*)d_in[3];
    const float* whhb = (const float*)d_in[4];
    float* out = (float*)d_out;
    (void)in_sizes; (void)n_in; (void)out_size;

    cudaFuncSetAttribute(gemm_mma, cudaFuncAttributeMaxDynamicSharedMemorySize, GM_SMEM);
    cudaFuncSetAttribute(lstm_f16, cudaFuncAttributeMaxDynamicSharedMemorySize, RS_SMEM);

    repack_w<<<dim3(G4, 8), 256>>>(wihf, whhf, wihb, whhb);
    conv_x_f16<<<MROWS * KDIM / 1024, 256>>>(x);

    for (int layer = 0; layer < 2; layer++) {
        zero_state<<<128, 512>>>();
        gemm_mma<<<dim3(G4 / 128, MROWS / 128, 2), 256, GM_SMEM>>>(layer);
        lstm_f16<<<NCTA, 512, RS_SMEM>>>(layer, out);
    }
}

// round 16
// speedup vs baseline: 1.1658x; 1.0165x over previous
#include <cuda_runtime.h>
#include <cuda_fp16.h>
#include <math.h>
#include <stdint.h>

// ---------------- problem constants ----------------
#define SEQ   256
#define BATCH 32
#define HID   1024
#define G4    4096
#define KDIM  1024
#define MROWS (SEQ*BATCH)

#define NCTA  128           // persistent grid (2 dirs x 64 j-tiles of 64 gate cols)
#define DCTA  64            // CTAs per direction

// output layout inside d_out (floats)
#define OUT_HALL   (SEQ*BATCH*2*HID)
#define OUT_CALL   (OUT_HALL + 2*BATCH*2*HID)

// ---------------- device scratch ----------------
__device__ float  g_xg  [2][SEQ*BATCH*G4];       // per-direction xg
__device__ __half g_Wih16[2][2][G4*KDIM];        // gate-permuted W_ih fp16 (input GEMM)
__device__ __half g_Whh16[2][2][G4*KDIM];        // gate-permuted W_hh fp16 (recurrence)
__device__ __half g_Axh[2][MROWS*KDIM];          // GEMM A hi ([0]=x layer0, [dir] layer1)
__device__ __half g_Axl[2][MROWS*KDIM];          // GEMM A lo
__device__ __half g_h16[2*2*BATCH*HID];          // [dir][pp][b][k] recurrent h fp16
__device__ unsigned g_sync[64];                  // counter per dir at g_sync[d*32] (128B pad)

// ---------------- sync / async-copy helpers ----------------
__device__ __forceinline__ unsigned ld_acq(const unsigned* p) {
    unsigned v; asm volatile("ld.acquire.gpu.u32 %0, [%1];" : "=r"(v) : "l"(p) : "memory"); return v;
}
__device__ __forceinline__ void red_rel_add(unsigned* p, unsigned v) {
    asm volatile("red.release.gpu.add.u32 [%0], %1;" :: "l"(p), "r"(v) : "memory");
}
__device__ __forceinline__ void cp16(uint32_t s, const void* g) {
    asm volatile("cp.async.cg.shared.global [%0], [%1], 16;" :: "r"(s), "l"(g));
}
__device__ __forceinline__ void cp_commit() { asm volatile("cp.async.commit_group;"); }
__device__ __forceinline__ void cp_wait1()  { asm volatile("cp.async.wait_group 1;" ::: "memory"); }
__device__ __forceinline__ void cp_wait0()  { asm volatile("cp.async.wait_group 0;" ::: "memory"); }

__device__ __forceinline__ uint32_t smem_u32(const void* p) {
    return (uint32_t)__cvta_generic_to_shared(p);
}

// ---------------- mma.sync / ldmatrix helpers (base PTX, sm_80+) ----------------
__device__ __forceinline__ void ldsm_x4(uint32_t& r0, uint32_t& r1, uint32_t& r2, uint32_t& r3,
                                        uint32_t addr) {
    asm volatile("ldmatrix.sync.aligned.m8n8.x4.shared.b16 {%0,%1,%2,%3}, [%4];"
                 : "=r"(r0), "=r"(r1), "=r"(r2), "=r"(r3) : "r"(addr));
}
__device__ __forceinline__ void ldsm_x2(uint32_t& r0, uint32_t& r1, uint32_t addr) {
    asm volatile("ldmatrix.sync.aligned.m8n8.x2.shared.b16 {%0,%1}, [%2];"
                 : "=r"(r0), "=r"(r1) : "r"(addr));
}
__device__ __forceinline__ void mma_f16(float& c0, float& c1, float& c2, float& c3,
                                        uint32_t a0, uint32_t a1, uint32_t a2, uint32_t a3,
                                        uint32_t b0, uint32_t b1) {
    asm volatile("mma.sync.aligned.m16n8k16.row.col.f32.f16.f16.f32 "
                 "{%0,%1,%2,%3}, {%4,%5,%6,%7}, {%8,%9}, {%0,%1,%2,%3};"
                 : "+f"(c0), "+f"(c1), "+f"(c2), "+f"(c3)
                 : "r"(a0), "r"(a1), "r"(a2), "r"(a3), "r"(b0), "r"(b1));
}

// ---------------- split helper ----------------
__device__ __forceinline__ void split_f16(float x, __half& h, __half& l) {
    h = __float2half_rn(x);
    l = __float2half_rn(x - __half2float(h));
}

// ---------------- 1a) weight gate-permute to fp16: row g*H+h -> 4h+g ----------------
__global__ __launch_bounds__(256) void repack_w(
    const float* __restrict__ wihf, const float* __restrict__ whhf,
    const float* __restrict__ wihb, const float* __restrict__ whhb)
{
    int p = blockIdx.x;
    int m = blockIdx.y;
    int dir   = m >> 2;
    int typ   = (m >> 1) & 1;          // 0 = ih, 1 = hh
    int layer = m & 1;
    int srow  = (p & 3) * HID + (p >> 2);

    const float* base = dir ? (typ ? whhb : wihb) : (typ ? whhf : wihf);
    const float* src  = base + (size_t)layer * G4 * KDIM;
    __half* dst = (typ ? g_Whh16[layer][dir] : g_Wih16[layer][dir]) + (size_t)p * KDIM;

    int c = threadIdx.x * 4;
    float4 v = *(const float4*)&src[(size_t)srow * KDIM + c];
    __half2 a = {__float2half_rn(v.x), __float2half_rn(v.y)};
    __half2 b = {__float2half_rn(v.z), __float2half_rn(v.w)};
    *(__half2*)&dst[c]     = a;
    *(__half2*)&dst[c + 2] = b;
}

// ---------------- 1b) fp32 x -> fp16 hi/lo for layer-0 GEMM A ----------------
__global__ __launch_bounds__(256) void conv_x_f16(const float* __restrict__ x)
{
    size_t i = ((size_t)blockIdx.x * 256 + threadIdx.x) * 4;
    float4 v = *(const float4*)&x[i];
    __half h0, l0, h1, l1, h2, l2, h3, l3;
    split_f16(v.x, h0, l0); split_f16(v.y, h1, l1);
    split_f16(v.z, h2, l2); split_f16(v.w, h3, l3);
    __half2 hh0 = {h0, h1}, hh1 = {h2, h3};
    __half2 ll0 = {l0, l1}, ll1 = {l2, l3};
    *(__half2*)&g_Axh[0][i]     = hh0; *(__half2*)&g_Axh[0][i + 2] = hh1;
    *(__half2*)&g_Axl[0][i]     = ll0; *(__half2*)&g_Axl[0][i + 2] = ll1;
}

// ---------------- 2) zero recurrent h + barrier counters ----------------
__global__ __launch_bounds__(512) void zero_state() {
    int i = blockIdx.x * blockDim.x + threadIdx.x;
    if (i < 64) g_sync[i] = 0u;
    ((uint32_t*)g_h16)[i] = 0u;
}

// ---------------- 3) input GEMM: fp16 2-term, BM=128 BN=128 BK=32 (R11 2-stage) --------
// 8 warps (4m x 2n), warp tile 32m x 64n. Stage(ch+1) issued BEFORE cp_wait1 so the
// prefetch stays a full chunk ahead (measured fastest: 706us, tensor 64%).
#define GM_SA  40
#define GM_AH  0
#define GM_AL  5120
#define GM_WH  10240
#define GM_STG 15360
#define GM_SMEM (2 * GM_STG * 2)

__global__ __launch_bounds__(256, 2) void gemm_mma(int layer)
{
    extern __shared__ __half gsm[];

    int tid = threadIdx.x;
    int wid = tid >> 5;
    int lane = tid & 31;
    int dir = blockIdx.z;
    int n0 = blockIdx.x * 128;
    int m0 = blockIdx.y * 128;

    const __half* Ah = g_Axh[layer == 0 ? 0 : dir];
    const __half* Al = g_Axl[layer == 0 ? 0 : dir];
    const __half* W  = g_Wih16[layer][dir];

    uint32_t sb = smem_u32(gsm);

    int arow0 = tid >> 2, aq = tid & 3;
    auto stage = [&](int buf, int k0) {
        uint32_t base = sb + buf * GM_STG * 2;
#pragma unroll
        for (int i = 0; i < 2; i++) {
            int row = arow0 + i * 64;
            uint32_t d = base + (row * GM_SA + aq * 8) * 2;
            size_t s = (size_t)(m0 + row) * KDIM + k0 + aq * 8;
            cp16(d + GM_AH * 2, Ah + s);
            cp16(d + GM_AL * 2, Al + s);
        }
#pragma unroll
        for (int i = 0; i < 2; i++) {
            int idx = tid + i * 256;
            int row = idx >> 2, q = idx & 3;
            uint32_t d = base + (row * GM_SA + q * 8) * 2 + GM_WH * 2;
            cp16(d, W + (size_t)(n0 + row) * KDIM + k0 + q * 8);
        }
        cp_commit();
    };

    int m0w = (wid >> 1) * 32;
    int n0w = (wid & 1) * 64;
    int a_row = m0w + (lane & 15);
    int a_col = (lane >> 4) * 8;
    int w_n   = n0w + ((lane >> 4) & 1) * 8 + (lane & 7);
    int w_col = ((lane >> 3) & 1) * 8;

    float acc[2][8][4];
#pragma unroll
    for (int mi = 0; mi < 2; mi++)
#pragma unroll
        for (int j = 0; j < 8; j++)
#pragma unroll
            for (int e = 0; e < 4; e++) acc[mi][j][e] = 0.0f;

    stage(0, 0);
    int buf = 0;
#pragma unroll 1
    for (int ch = 0; ch < KDIM / 32; ch++) {
        if (ch < KDIM / 32 - 1) { stage(buf ^ 1, (ch + 1) * 32); cp_wait1(); }
        else                    { cp_wait0(); }
        __syncthreads();
        uint32_t base = sb + buf * GM_STG * 2;
#pragma unroll
        for (int ks = 0; ks < 2; ks++) {
            uint32_t aH[2][4], aL[2][4], wH[4][4];
#pragma unroll
            for (int mi = 0; mi < 2; mi++) {
                uint32_t ao = base + ((a_row + mi * 16) * GM_SA + ks * 16 + a_col) * 2;
                ldsm_x4(aH[mi][0], aH[mi][1], aH[mi][2], aH[mi][3], ao + GM_AH * 2);
                ldsm_x4(aL[mi][0], aL[mi][1], aL[mi][2], aL[mi][3], ao + GM_AL * 2);
            }
#pragma unroll
            for (int jp = 0; jp < 4; jp++) {
                uint32_t wo = base + ((w_n + jp * 16) * GM_SA + ks * 16 + w_col) * 2;
                ldsm_x4(wH[jp][0], wH[jp][1], wH[jp][2], wH[jp][3], wo + GM_WH * 2);
            }
#pragma unroll
            for (int mi = 0; mi < 2; mi++) {
#pragma unroll
                for (int j = 0; j < 8; j++) {
                    int jp = j >> 1, hi = (j & 1) * 2;
                    float* c = acc[mi][j];
                    mma_f16(c[0], c[1], c[2], c[3],
                            aH[mi][0], aH[mi][1], aH[mi][2], aH[mi][3],
                            wH[jp][hi], wH[jp][hi + 1]);
                    mma_f16(c[0], c[1], c[2], c[3],
                            aL[mi][0], aL[mi][1], aL[mi][2], aL[mi][3],
                            wH[jp][hi], wH[jp][hi + 1]);
                }
            }
        }
        __syncthreads();
        buf ^= 1;
    }

    float* C = g_xg[dir];
    int g = lane >> 2, q = lane & 3;
#pragma unroll
    for (int mi = 0; mi < 2; mi++) {
        int row = m0 + m0w + mi * 16 + g;
#pragma unroll
        for (int j = 0; j < 8; j++) {
            int col = n0 + n0w + j * 8 + q * 2;
            float2 v0 = { acc[mi][j][0], acc[mi][j][1] };
            float2 v1 = { acc[mi][j][2], acc[mi][j][3] };
            *(float2*)&C[(size_t)row * G4 + col]       = v0;
            *(float2*)&C[(size_t)(row + 8) * G4 + col] = v1;
        }
    }
}

// ---------------- 4) persistent recurrent kernel: pipelined h staging ----------------
// 128 CTAs x 512 threads (16 warps). dir = cta>>6, jt = cta&63 -> gate cols [jt*64,+64).
// Warp w: k-slice ksl = w>>1 (k in [ksl*128,+128)), n-column nc = w&1 (j in [nc*32,+32)).
// W fragments in registers. Per step the h tile is staged in TWO chunks, where chunk c
// holds halves [s*128 + c*64, +64) of EVERY slice s — so both MMA halves engage all 16
// warps and chunk1's L2 latency hides under the first MMA half.
#define RS_A     0
#define RS_ASTR  1032            // A row stride in halves
#define RS_P     66560
#define RS_PSTR  68              // partials row stride in floats
#define RS_PSLC  (32 * RS_PSTR)  // floats per slice (2176)
#define RS_SMEM  (RS_P + 8 * RS_PSLC * 4)   // 136192

__global__ __launch_bounds__(512, 1) void lstm_f16(int layer, float* __restrict__ dout)
{
    extern __shared__ char sm8[];
    uint32_t sb = smem_u32(sm8);
    float* part = (float*)(sm8 + RS_P);

    int tid  = threadIdx.x;
    int wid  = tid >> 5;
    int lane = tid & 31;
    int cta  = blockIdx.x;
    int d    = cta >> 6;
    int jt   = cta & 63;
    int j0g  = jt * 64;
    int hbase = jt * 16;
    int ksl = wid >> 1;          // k slice 0..7
    int nc  = wid & 1;           // n column 0..1

    const __half* WhG = g_Whh16[layer][d];
    const float* xgb = g_xg[d];
    __half* hb = g_h16 + (size_t)d * 2 * BATCH * HID;   // [pp][b][k]

    unsigned* cnt = &g_sync[d * 32];

    // ---- prologue: W fragments into registers (2 smem staging passes) ----
    uint32_t wf[8][4][2];
#pragma unroll 1
    for (int p = 0; p < 2; p++) {
#pragma unroll
        for (int i = 0; i < 8; i++) {
            int idx = tid + i * 512;
            int r = idx >> 6, g = idx & 63;
            cp16(sb + RS_A + (uint32_t)(r * 1040 + g * 16),
                 WhG + (size_t)(j0g + r) * KDIM + p * 512 + g * 8);
        }
        cp_commit(); cp_wait0(); __syncthreads();
        if ((ksl >> 2) == p) {
            int lk = (ksl & 3) * 128;
#pragma unroll
            for (int ks = 0; ks < 8; ks++)
#pragma unroll
                for (int nt = 0; nt < 4; nt++) {
                    uint32_t addr = sb + RS_A
                        + (uint32_t)((nc * 32 + nt * 8 + (lane & 7)) * 1040
                                     + (lk + ks * 16 + ((lane >> 3) & 1) * 8) * 2);
                    ldsm_x2(wf[ks][nt][0], wf[ks][nt][1], addr);
                }
        }
        __syncthreads();
    }

    uint32_t a_lane = (uint32_t)((lane & 15) * (RS_ASTR * 2) + (lane >> 4) * 16);
    int b  = tid & 31;
    int hl = tid >> 5;            // 0..15 (one hidden index per thread)
    float c_reg = 0.0f;

    // staging decomposition: idx = tid + i*512 in [0,2048): r = idx>>6, s = (idx>>3)&7, q = idx&7
    int s_r = tid >> 6;                 // +8 per i? no: recompute from idx each iter
    (void)s_r;

    for (int t = 0; t < SEQ; t++) {
        int time = d ? (SEQ - 1 - t) : t;
        int rp = t & 1, wp = rp ^ 1;
        const __half* hin = hb + (size_t)rp * BATCH * HID;

        // xg prefetch (consumed in pointwise)
        float4 xv = *(const float4*)(xgb + (size_t)time * BATCH * G4
                                     + (size_t)b * G4 + j0g + hl * 4);

        // ---- stage h in two chunks: chunk c covers halves [s*128 + c*64, +64) per slice s
        auto stageh = [&](int c) {
#pragma unroll
            for (int i = 0; i < 4; i++) {
                int idx = tid + i * 512;            // 0..2047
                int r = idx >> 6;                   // 0..31
                int s = (idx >> 3) & 7;             // 0..7
                int q = idx & 7;                    // 0..7
                int col = s * 128 + c * 64 + q * 8; // halves
                cp16(sb + RS_A + (uint32_t)(r * (RS_ASTR * 2) + col * 2),
                     hin + (size_t)r * HID + col);
            }
            cp_commit();
        };
        stageh(0);
        stageh(1);

        float acc[2][4][4];
#pragma unroll
        for (int mi = 0; mi < 2; mi++)
#pragma unroll
            for (int nt = 0; nt < 4; nt++)
#pragma unroll
                for (int e = 0; e < 4; e++) acc[mi][nt][e] = 0.0f;

        uint32_t ab = sb + RS_A + a_lane + (uint32_t)(ksl * 256);

        // ---- half 1: chunk0 ready, chunk1 in flight ----
        cp_wait1(); __syncthreads();
#pragma unroll
        for (int ks = 0; ks < 4; ks++) {
            uint32_t a0[4], a1[4];
            ldsm_x4(a0[0], a0[1], a0[2], a0[3], ab + ks * 32);
            ldsm_x4(a1[0], a1[1], a1[2], a1[3], ab + 16 * (RS_ASTR * 2) + ks * 32);
#pragma unroll
            for (int nt = 0; nt < 4; nt++) {
                mma_f16(acc[0][nt][0], acc[0][nt][1], acc[0][nt][2], acc[0][nt][3],
                        a0[0], a0[1], a0[2], a0[3], wf[ks][nt][0], wf[ks][nt][1]);
                mma_f16(acc[1][nt][0], acc[1][nt][1], acc[1][nt][2], acc[1][nt][3],
                        a1[0], a1[1], a1[2], a1[3], wf[ks][nt][0], wf[ks][nt][1]);
            }
        }
        // ---- half 2 ----
        cp_wait0(); __syncthreads();
#pragma unroll
        for (int ks = 4; ks < 8; ks++) {
            uint32_t a0[4], a1[4];
            ldsm_x4(a0[0], a0[1], a0[2], a0[3], ab + ks * 32);
            ldsm_x4(a1[0], a1[1], a1[2], a1[3], ab + 16 * (RS_ASTR * 2) + ks * 32);
#pragma unroll
            for (int nt = 0; nt < 4; nt++) {
                mma_f16(acc[0][nt][0], acc[0][nt][1], acc[0][nt][2], acc[0][nt][3],
                        a0[0], a0[1], a0[2], a0[3], wf[ks][nt][0], wf[ks][nt][1]);
                mma_f16(acc[1][nt][0], acc[1][nt][1], acc[1][nt][2], acc[1][nt][3],
                        a1[0], a1[1], a1[2], a1[3], wf[ks][nt][0], wf[ks][nt][1]);
            }
        }

        // ---- partials -> smem slice ksl ----
        {
            int g = lane >> 2, q = lane & 3;
            float* pbase = part + ksl * RS_PSLC;
#pragma unroll
            for (int mi = 0; mi < 2; mi++)
#pragma unroll
                for (int nt = 0; nt < 4; nt++) {
                    int jj = nc * 32 + nt * 8 + q * 2;
                    float2 v0 = { acc[mi][nt][0], acc[mi][nt][1] };
                    float2 v1 = { acc[mi][nt][2], acc[mi][nt][3] };
                    *(float2*)&pbase[(mi * 16 + g) * RS_PSTR + jj]     = v0;
                    *(float2*)&pbase[(mi * 16 + g + 8) * RS_PSTR + jj] = v1;
                }
        }
        __syncthreads();

        // ---- pointwise: thread owns (b, hl); reduce 8 slices ----
        float gi = xv.x, gf = xv.y, gg = xv.z, go = xv.w;
#pragma unroll
        for (int s = 0; s < 8; s++) {
            float4 v = *(const float4*)&part[s * RS_PSLC + b * RS_PSTR + hl * 4];
            gi += v.x; gf += v.y; gg += v.z; go += v.w;
        }

        float iv = 1.0f / (1.0f + expf(-gi));
        float fv = 1.0f / (1.0f + expf(-gf));
        float gv = tanhf(gg);
        float ov = 1.0f / (1.0f + expf(-go));

        float c = fv * c_reg + iv * gv;
        float hn = ov * tanhf(c);
        c_reg = c;

        int hg = hbase + hl;
        __half hh, hlw;
        split_f16(hn, hh, hlw);
        hb[(size_t)wp * BATCH * HID + (size_t)b * HID + hg] = hh;

        if (layer == 0) {
            size_t arow = ((size_t)time * BATCH + b) * KDIM + hg;
            g_Axh[d][arow] = hh;
            g_Axl[d][arow] = hlw;
        } else {
            dout[(size_t)time * BATCH * 2 * HID + (size_t)b * 2 * HID + d * HID + hg] = hn;
        }
        if (time == SEQ - 1) {
            dout[OUT_HALL + (size_t)layer * BATCH * 2 * HID + (size_t)b * 2 * HID + d * HID + hg] = hn;
            dout[OUT_CALL + (size_t)layer * BATCH * 2 * HID + (size_t)b * 2 * HID + d * HID + hg] = c;
        }

        // ---- per-direction counter barrier: release-red arrive, acquire poll ----
        if (t < SEQ - 1) {
            __syncthreads();
            if (tid == 0) {
                red_rel_add(cnt, 1u);
                unsigned target = (unsigned)((t + 1) * DCTA);
                while (ld_acq(cnt) < target) { }
            }
            __syncthreads();
        }
    }
}

// ---------------- host launcher ----------------
extern "C" void kernel_launch(void* const* d_in, const int* in_sizes, int n_in,
                              void* d_out, int out_size)
{
    const float* x    = (const float*)d_in[0];
    const float* wihf = (const float*)d_in[1];
    const float* whhf = (const float*)d_in[2];
    const float* wihb = (const float*)d_in[3];
    const float* whhb = (const float*)d_in[4];
    float* out = (float*)d_out;
    (void)in_sizes; (void)n_in; (void)out_size;

    cudaFuncSetAttribute(gemm_mma, cudaFuncAttributeMaxDynamicSharedMemorySize, GM_SMEM);
    cudaFuncSetAttribute(lstm_f16, cudaFuncAttributeMaxDynamicSharedMemorySize, RS_SMEM);

    repack_w<<<dim3(G4, 8), 256>>>(wihf, whhf, wihb, whhb);
    conv_x_f16<<<MROWS * KDIM / 1024, 256>>>(x);

    for (int layer = 0; layer < 2; layer++) {
        zero_state<<<128, 512>>>();
        gemm_mma<<<dim3(G4 / 128, MROWS / 128, 2), 256, GM_SMEM>>>(layer);
        lstm_f16<<<NCTA, 512, RS_SMEM>>>(layer, out);
    }
}